// round 15
// baseline (speedup 1.0000x reference)
#include <cuda_runtime.h>
#include <cuda_bf16.h>

// CubePad: x [6N, C, 256, 256] -> out [6N, C, 258, 258]
// Face order: 0 front, 1 right, 2 back, 3 left, 4 top, 5 down.
//
// FINAL. Block-partitioned fused kernel: first `plate_blocks` CTAs write the
// top/down plate rows (r=0, r=257); the rest write middle rows, one warp per
// row pair, full-row STG.128 with parity-dependent layout, side borders fused
// into the row stores. All border/plate sources are (offset, stride) pairs
// off a single base pointer -> 32 regs, ~84% occupancy.
//
// Roofline verdict (14 rounds): compulsory L2-side movement is 812MB
// (406 read + 406 write); at the HW-measured path-independent ~6300 B/cyc
// LTS chip cap the floor is ~67us. Eight structural variants and all four
// ld/st cache-policy combinations converge to 67.1-68.2us ncu — this is the
// machine ceiling for the op. This configuration benched best and most
// reproducibly.

#define Hh 256
#define Ww 256
#define Cc 64
#define HP 258
#define WP 258
#define FACE_IN  (Hh * Ww)
#define FACE_OUT (HP * WP)
#define CF       (Cc * FACE_IN)   // face stride in floats

__device__ __forceinline__ void store_even_row(
    float* orow, float4 v1, float4 v2, float lval, float rval, int lane)
{
    // even r: orow 16B aligned; vectors cover cols 0..255, STG.64 leftover
    float prev = __shfl_up_sync(0xffffffffu, v2.w, 1);
    float4 o1 = make_float4(lane == 0 ? lval : prev, v1.x, v1.y, v1.z);
    float4 o2 = make_float4(v1.w, v2.x, v2.y, v2.z);
    reinterpret_cast<float4*>(orow)[lane * 2]     = o1;
    reinterpret_cast<float4*>(orow)[lane * 2 + 1] = o2;
    if (lane == 31)
        *reinterpret_cast<float2*>(orow + 256) = make_float2(v2.w, rval);
}

__device__ __forceinline__ void store_odd_row(
    float* orow, float4 v1, float4 v2, float lval, float rval, int lane)
{
    // odd r: orow+2 16B aligned; vectors cover cols 2..257, STG.64 leftover
    float nxt = __shfl_down_sync(0xffffffffu, v1.x, 1);
    float4 o1 = make_float4(v1.y, v1.z, v1.w, v2.x);
    float4 o2 = make_float4(v2.y, v2.z, v2.w, lane == 31 ? rval : nxt);
    reinterpret_cast<float4*>(orow + 2)[lane * 2]     = o1;
    reinterpret_cast<float4*>(orow + 2)[lane * 2 + 1] = o2;
    if (lane == 0)
        *reinterpret_cast<float2*>(orow) = make_float2(lval, v1.x);
}

__global__ void __launch_bounds__(256, 7) cubepad_final(
    const float* __restrict__ in, float* __restrict__ out,
    int plate_blocks, int total_plate_warps, int total_int_warps)
{
    int wid  = threadIdx.x >> 5;
    int lane = threadIdx.x & 31;
    int b    = blockIdx.x;

    if (b >= plate_blocks) {
        // ---------------- interior: one warp per row pair ----------------
        int idx = (b - plate_blocks) * 8 + wid;
        if (idx >= total_int_warps) return;
        int g   = idx & 127;          // row pair 0..127
        int nfc = idx >> 7;
        int nf  = nfc >> 6;           // n*6 + f
        int f   = nf % 6;
        const float* base = in + (nfc - f * Cc) * FACE_IN;
        float* oface = out + nfc * FACE_OUT;

        int ho = g * 2;               // odd output row r = ho+1
        int he = ho + 1;              // even output row r = he+1
        const float* self = base + f * CF + ho * Ww;

        float4 a1 = reinterpret_cast<const float4*>(self)[lane * 2];
        float4 a2 = reinterpret_cast<const float4*>(self)[lane * 2 + 1];
        float4 b1 = reinterpret_cast<const float4*>(self + Ww)[lane * 2];
        float4 b2 = reinterpret_cast<const float4*>(self + Ww)[lane * 2 + 1];

        // side-border sources: val(h) = base[off + h*str]
        int loff, lstr, roff, rstr;
        switch (f) {
            case 0: loff = 3*CF + (Ww-1); lstr = Ww;  roff = 1*CF; rstr = Ww; break;
            case 1: loff = 0*CF + (Ww-1); lstr = Ww;  roff = 2*CF; rstr = Ww; break;
            case 2: loff = 1*CF + (Ww-1); lstr = Ww;  roff = 3*CF; rstr = Ww; break;
            case 3: loff = 2*CF + (Ww-1); lstr = Ww;  roff = 0*CF; rstr = Ww; break;
            case 4: loff = 3*CF;          lstr = 1;
                    roff = 1*CF + (Ww-1); rstr = -1;  break;
            default:loff = 3*CF + (Hh-1)*Ww + (Ww-1); lstr = -1;
                    roff = 1*CF + (Hh-1)*Ww;          rstr = 1;   break;
        }
        const float* lp = base + loff + ho * lstr;
        const float* rp = base + roff + ho * rstr;
        float la = lp[0], lb = lp[lstr];
        float ra = rp[0], rb = rp[rstr];

        store_odd_row (oface + (ho + 1) * WP, a1, a2, la, ra, lane);
        store_even_row(oface + (he + 1) * WP, b1, b2, lb, rb, lane);
    } else {
        // ---------------- plates: one warp per plate row ----------------
        int idx = b * 8 + wid;
        if (idx >= total_plate_warps) return;
        int nfc    = idx >> 1;
        bool is_top = (idx & 1) == 0;
        int nf = nfc >> 6;
        int f  = nf % 6;
        const float* base = in + (nfc - f * Cc) * FACE_IN;
        float* orow = out + nfc * FACE_OUT + (is_top ? 0 : (HP - 1) * WP);

        // plate source: val(w) = base[off + w*str]
        int off, str;
        if (is_top) {
            switch (f) {
                case 0:  off = 4*CF + (Hh-1)*Ww;          str = 1;   break;
                case 1:  off = 4*CF + (Hh-1)*Ww + (Ww-1); str = -Ww; break;
                case 2:  off = 4*CF + (Ww-1);             str = -1;  break;
                case 3:  off = 4*CF;                      str = Ww;  break;
                case 4:  off = 2*CF + (Ww-1);             str = -1;  break;
                default: off = 0*CF + (Hh-1)*Ww;          str = 1;   break;
            }
        } else {
            switch (f) {
                case 0:  off = 5*CF;                      str = 1;   break;
                case 1:  off = 5*CF + (Ww-1);             str = Ww;  break;
                case 2:  off = 5*CF + (Hh-1)*Ww + (Ww-1); str = -1;  break;
                case 3:  off = 5*CF + (Hh-1)*Ww;          str = -Ww; break;
                case 4:  off = 0*CF;                      str = 1;   break;
                default: off = 2*CF + (Hh-1)*Ww + (Ww-1); str = -1;  break;
            }
        }
        #pragma unroll
        for (int col = lane; col < WP; col += 32) {
            int w = col - 1;
            if (w < 0) w = 0;
            if (w > Ww - 1) w = Ww - 1;
            orow[col] = base[off + w * str];
        }
    }
}

extern "C" void kernel_launch(void* const* d_in, const int* in_sizes, int n_in,
                              void* d_out, int out_size)
{
    const float* x = (const float*)d_in[0];
    float* out = (float*)d_out;

    int total_in  = in_sizes[0];                 // 6N * C * H * W
    int nfc_total = total_in / FACE_IN;          // 6N * C

    int total_plate_warps = nfc_total * 2;
    int total_int_warps   = nfc_total * 128;     // one warp per row pair
    int plate_blocks = (total_plate_warps + 7) / 8;
    int int_blocks   = (total_int_warps + 7) / 8;

    cubepad_final<<<plate_blocks + int_blocks, 256>>>(
        x, out, plate_blocks, total_plate_warps, total_int_warps);
}

// round 16
// speedup vs baseline: 1.0193x; 1.0193x over previous
#include <cuda_runtime.h>
#include <cuda_bf16.h>

// CubePad: x [6N, C, 256, 256] -> out [6N, C, 258, 258]
// Face order: 0 front, 1 right, 2 back, 3 left, 4 top, 5 down.
//
// FINAL (locked). Block-partitioned fused kernel: first `plate_blocks` CTAs
// write the top/down plate rows (r=0, r=257); the rest write middle rows, one
// warp per row pair, full-row STG.128 with parity-dependent layout, side
// borders fused into the row stores. All border/plate sources are
// (offset, stride) pairs off a single base pointer -> 32 regs.
//
// Roofline verdict (15 rounds): compulsory L2-side movement is 812MB
// (406 read + 406 write); at the HW-measured path-independent ~6300 B/cyc
// LTS chip cap the floor is ~67us. Eight structural variants, the full ld/st
// cache-policy 2x2, grid reorderings, and MLP/occupancy sweeps (occ 40-89%)
// all converge to 67.1-68.4us ncu — the machine ceiling for this op.

#define Hh 256
#define Ww 256
#define Cc 64
#define HP 258
#define WP 258
#define FACE_IN  (Hh * Ww)
#define FACE_OUT (HP * WP)
#define CF       (Cc * FACE_IN)   // face stride in floats

__device__ __forceinline__ void store_even_row(
    float* orow, float4 v1, float4 v2, float lval, float rval, int lane)
{
    // even r: orow 16B aligned; vectors cover cols 0..255, STG.64 leftover
    float prev = __shfl_up_sync(0xffffffffu, v2.w, 1);
    float4 o1 = make_float4(lane == 0 ? lval : prev, v1.x, v1.y, v1.z);
    float4 o2 = make_float4(v1.w, v2.x, v2.y, v2.z);
    reinterpret_cast<float4*>(orow)[lane * 2]     = o1;
    reinterpret_cast<float4*>(orow)[lane * 2 + 1] = o2;
    if (lane == 31)
        *reinterpret_cast<float2*>(orow + 256) = make_float2(v2.w, rval);
}

__device__ __forceinline__ void store_odd_row(
    float* orow, float4 v1, float4 v2, float lval, float rval, int lane)
{
    // odd r: orow+2 16B aligned; vectors cover cols 2..257, STG.64 leftover
    float nxt = __shfl_down_sync(0xffffffffu, v1.x, 1);
    float4 o1 = make_float4(v1.y, v1.z, v1.w, v2.x);
    float4 o2 = make_float4(v2.y, v2.z, v2.w, lane == 31 ? rval : nxt);
    reinterpret_cast<float4*>(orow + 2)[lane * 2]     = o1;
    reinterpret_cast<float4*>(orow + 2)[lane * 2 + 1] = o2;
    if (lane == 0)
        *reinterpret_cast<float2*>(orow) = make_float2(lval, v1.x);
}

__global__ void __launch_bounds__(256, 7) cubepad_final(
    const float* __restrict__ in, float* __restrict__ out,
    int plate_blocks, int total_plate_warps, int total_int_warps)
{
    int wid  = threadIdx.x >> 5;
    int lane = threadIdx.x & 31;
    int b    = blockIdx.x;

    if (b >= plate_blocks) {
        // ---------------- interior: one warp per row pair ----------------
        int idx = (b - plate_blocks) * 8 + wid;
        if (idx >= total_int_warps) return;
        int g   = idx & 127;          // row pair 0..127
        int nfc = idx >> 7;
        int nf  = nfc >> 6;           // n*6 + f
        int f   = nf % 6;
        const float* base = in + (nfc - f * Cc) * FACE_IN;
        float* oface = out + nfc * FACE_OUT;

        int ho = g * 2;               // odd output row r = ho+1
        int he = ho + 1;              // even output row r = he+1
        const float* self = base + f * CF + ho * Ww;

        float4 a1 = reinterpret_cast<const float4*>(self)[lane * 2];
        float4 a2 = reinterpret_cast<const float4*>(self)[lane * 2 + 1];
        float4 b1 = reinterpret_cast<const float4*>(self + Ww)[lane * 2];
        float4 b2 = reinterpret_cast<const float4*>(self + Ww)[lane * 2 + 1];

        // side-border sources: val(h) = base[off + h*str]
        int loff, lstr, roff, rstr;
        switch (f) {
            case 0: loff = 3*CF + (Ww-1); lstr = Ww;  roff = 1*CF; rstr = Ww; break;
            case 1: loff = 0*CF + (Ww-1); lstr = Ww;  roff = 2*CF; rstr = Ww; break;
            case 2: loff = 1*CF + (Ww-1); lstr = Ww;  roff = 3*CF; rstr = Ww; break;
            case 3: loff = 2*CF + (Ww-1); lstr = Ww;  roff = 0*CF; rstr = Ww; break;
            case 4: loff = 3*CF;          lstr = 1;
                    roff = 1*CF + (Ww-1); rstr = -1;  break;
            default:loff = 3*CF + (Hh-1)*Ww + (Ww-1); lstr = -1;
                    roff = 1*CF + (Hh-1)*Ww;          rstr = 1;   break;
        }
        const float* lp = base + loff + ho * lstr;
        const float* rp = base + roff + ho * rstr;
        float la = lp[0], lb = lp[lstr];
        float ra = rp[0], rb = rp[rstr];

        store_odd_row (oface + (ho + 1) * WP, a1, a2, la, ra, lane);
        store_even_row(oface + (he + 1) * WP, b1, b2, lb, rb, lane);
    } else {
        // ---------------- plates: one warp per plate row ----------------
        int idx = b * 8 + wid;
        if (idx >= total_plate_warps) return;
        int nfc    = idx >> 1;
        bool is_top = (idx & 1) == 0;
        int nf = nfc >> 6;
        int f  = nf % 6;
        const float* base = in + (nfc - f * Cc) * FACE_IN;
        float* orow = out + nfc * FACE_OUT + (is_top ? 0 : (HP - 1) * WP);

        // plate source: val(w) = base[off + w*str]
        int off, str;
        if (is_top) {
            switch (f) {
                case 0:  off = 4*CF + (Hh-1)*Ww;          str = 1;   break;
                case 1:  off = 4*CF + (Hh-1)*Ww + (Ww-1); str = -Ww; break;
                case 2:  off = 4*CF + (Ww-1);             str = -1;  break;
                case 3:  off = 4*CF;                      str = Ww;  break;
                case 4:  off = 2*CF + (Ww-1);             str = -1;  break;
                default: off = 0*CF + (Hh-1)*Ww;          str = 1;   break;
            }
        } else {
            switch (f) {
                case 0:  off = 5*CF;                      str = 1;   break;
                case 1:  off = 5*CF + (Ww-1);             str = Ww;  break;
                case 2:  off = 5*CF + (Hh-1)*Ww + (Ww-1); str = -1;  break;
                case 3:  off = 5*CF + (Hh-1)*Ww;          str = -Ww; break;
                case 4:  off = 0*CF;                      str = 1;   break;
                default: off = 2*CF + (Hh-1)*Ww + (Ww-1); str = -1;  break;
            }
        }
        #pragma unroll
        for (int col = lane; col < WP; col += 32) {
            int w = col - 1;
            if (w < 0) w = 0;
            if (w > Ww - 1) w = Ww - 1;
            orow[col] = base[off + w * str];
        }
    }
}

extern "C" void kernel_launch(void* const* d_in, const int* in_sizes, int n_in,
                              void* d_out, int out_size)
{
    const float* x = (const float*)d_in[0];
    float* out = (float*)d_out;

    int total_in  = in_sizes[0];                 // 6N * C * H * W
    int nfc_total = total_in / FACE_IN;          // 6N * C

    int total_plate_warps = nfc_total * 2;
    int total_int_warps   = nfc_total * 128;     // one warp per row pair
    int plate_blocks = (total_plate_warps + 7) / 8;
    int int_blocks   = (total_int_warps + 7) / 8;

    cubepad_final<<<plate_blocks + int_blocks, 256>>>(
        x, out, plate_blocks, total_plate_warps, total_int_warps);
}